// round 6
// baseline (speedup 1.0000x reference)
#include <cuda_runtime.h>
#include <cuda_fp16.h>
#include <cstdint>

// ============================ problem constants ============================
#define M_TOT 8192
#define N_TOT 11008
#define K_TOT 4096
#define GSZ   128

#define BM 128
#define BN 128
#define BK 64
#define STAGES 3
#define KT (K_TOT / BK)        // 64
#define TILES_M (M_TOT / BM)   // 64
#define TILES_N (N_TOT / BN)   // 86

#define SA 72                              // padded row pitch in halves (144 B)
#define A_TILE_BYTES (BM * SA * 2)         // 18432
#define B_TILE_BYTES (BN * SA * 2)         // 18432
#define STAGE_BYTES  (A_TILE_BYTES + B_TILE_BYTES)
#define SMEM_TOTAL_BYTES (STAGES * STAGE_BYTES)  // 110592 -> 2 CTAs/SM

// scratch (f16 copies of x and dequantized weight)
__device__ __align__(1024) __half g_A[(size_t)M_TOT * K_TOT];  // 64 MiB
__device__ __align__(1024) __half g_B[(size_t)N_TOT * K_TOT];  // 86 MiB

// ============================ PTX helpers ============================
__device__ __forceinline__ uint32_t smem_to_u32(const void* p) {
    uint32_t a;
    asm("{ .reg .u64 t; cvta.to.shared.u64 t, %1; cvt.u32.u64 %0, t; }"
        : "=r"(a) : "l"(p));
    return a;
}

__device__ __forceinline__ void cp_async16(uint32_t saddr, const void* gptr) {
    asm volatile("cp.async.cg.shared.global [%0], [%1], 16;"
                 :: "r"(saddr), "l"(gptr) : "memory");
}
__device__ __forceinline__ void cp_async_commit() {
    asm volatile("cp.async.commit_group;" ::: "memory");
}
template <int N>
__device__ __forceinline__ void cp_async_wait() {
    asm volatile("cp.async.wait_group %0;" :: "n"(N) : "memory");
}

__device__ __forceinline__ void ldsm_x4(uint32_t& r0, uint32_t& r1,
                                        uint32_t& r2, uint32_t& r3, uint32_t a) {
    asm volatile("ldmatrix.sync.aligned.m8n8.x4.shared.b16 {%0,%1,%2,%3}, [%4];"
                 : "=r"(r0), "=r"(r1), "=r"(r2), "=r"(r3) : "r"(a));
}

__device__ __forceinline__ void mma_16816(float& c0, float& c1, float& c2, float& c3,
                                          uint32_t a0, uint32_t a1, uint32_t a2, uint32_t a3,
                                          uint32_t b0, uint32_t b1) {
    asm volatile(
        "mma.sync.aligned.m16n8k16.row.col.f32.f16.f16.f32 "
        "{%0,%1,%2,%3}, {%4,%5,%6,%7}, {%8,%9}, {%0,%1,%2,%3};"
        : "+f"(c0), "+f"(c1), "+f"(c2), "+f"(c3)
        : "r"(a0), "r"(a1), "r"(a2), "r"(a3), "r"(b0), "r"(b1));
}

// ============================ fused prep kernel ============================
// blocks [0, XB)          : x f32 -> f16
// blocks [XB, XB + WB)    : weight int8(int32) dequant -> f16
#define XB ((int)(((size_t)M_TOT * K_TOT / 8) / 256))   // 16384
#define WB ((int)(((size_t)N_TOT * K_TOT / 8) / 256))   // 22016

__global__ void __launch_bounds__(256) prep_kernel(
    const float* __restrict__ x,
    const int*   __restrict__ w,
    const float* __restrict__ sz,
    __half* __restrict__ oA,
    __half* __restrict__ oB)
{
    int b = blockIdx.x;
    if (b < XB) {
        size_t i = ((size_t)b * 256 + threadIdx.x) * 8;
        float4 a = *reinterpret_cast<const float4*>(x + i);
        float4 c = *reinterpret_cast<const float4*>(x + i + 4);
        __half2 h0 = __floats2half2_rn(a.x, a.y);
        __half2 h1 = __floats2half2_rn(a.z, a.w);
        __half2 h2 = __floats2half2_rn(c.x, c.y);
        __half2 h3 = __floats2half2_rn(c.z, c.w);
        uint4 v;
        v.x = *reinterpret_cast<uint32_t*>(&h0);
        v.y = *reinterpret_cast<uint32_t*>(&h1);
        v.z = *reinterpret_cast<uint32_t*>(&h2);
        v.w = *reinterpret_cast<uint32_t*>(&h3);
        *reinterpret_cast<uint4*>(oA + i) = v;
    } else {
        int idx = (b - XB) * 256 + threadIdx.x;
        int oo = idx >> 9;               // output feature (row)
        int i0 = (idx & 511) << 3;       // start col (8 per thread)
        int g  = i0 >> 7;                // group index
        float2 s2 = reinterpret_cast<const float2*>(sz)[(size_t)g * N_TOT + oo];
        float s = s2.x, z = s2.y;
        size_t base = (size_t)oo * K_TOT + i0;
        int4 wa = reinterpret_cast<const int4*>(w + base)[0];
        int4 wb = reinterpret_cast<const int4*>(w + base)[1];
        __half2 h0 = __floats2half2_rn(wa.x * s + z, wa.y * s + z);
        __half2 h1 = __floats2half2_rn(wa.z * s + z, wa.w * s + z);
        __half2 h2 = __floats2half2_rn(wb.x * s + z, wb.y * s + z);
        __half2 h3 = __floats2half2_rn(wb.z * s + z, wb.w * s + z);
        uint4 v;
        v.x = *reinterpret_cast<uint32_t*>(&h0);
        v.y = *reinterpret_cast<uint32_t*>(&h1);
        v.z = *reinterpret_cast<uint32_t*>(&h2);
        v.w = *reinterpret_cast<uint32_t*>(&h3);
        *reinterpret_cast<uint4*>(oB + base) = v;
    }
}

// ============================ GEMM kernel ============================
// 256 threads = 8 warps; warp grid 4 (m) x 2 (n); warp tile 32x64.
// mma m16n8k16: 2 m-frags x 8 n-frags per warp; B loaded pairwise via x4.
// 16 warps/SM (2 CTAs) -> 4 warps/SMSP to hide barriers + LDS latency.
__global__ void __launch_bounds__(256, 2) gemm_kernel(
    const float* __restrict__ bias,
    float* __restrict__ out)
{
    extern __shared__ __align__(128) char smem[];
    uint32_t sb = smem_to_u32(smem);

    int tid = threadIdx.x;
    int wid = tid >> 5;
    int lane = tid & 31;
    int warp_m = wid & 3;    // 0..3
    int warp_n = wid >> 2;   // 0..1

    // L2-friendly raster
    int pid = blockIdx.x;
    const int GROUP_M = 16;
    const int npg = GROUP_M * TILES_N;
    int gidx = pid / npg;
    int r = pid - gidx * npg;
    int pid_m = gidx * GROUP_M + (r % GROUP_M);
    int pid_n = r / GROUP_M;

    const __half* Ag = g_A + (size_t)(pid_m * BM) * K_TOT;
    const __half* Bg = g_B + (size_t)(pid_n * BN) * K_TOT;

    // per-thread load coords: 1024 chunks of 16B per operand per stage; 4 each
    int lrow[4], lch[4];
    #pragma unroll
    for (int i = 0; i < 4; ++i) {
        int idx = tid + i * 256;
        lrow[i] = idx >> 3;
        lch[i]  = idx & 7;
    }

    auto issue_stage = [&](int s, int kt) {
        int k0 = kt * BK;
        uint32_t sa = sb + s * STAGE_BYTES;
        uint32_t sbb = sa + A_TILE_BYTES;
        #pragma unroll
        for (int i = 0; i < 4; ++i) {
            uint32_t off = (uint32_t)(lrow[i] * SA + lch[i] * 8) * 2;
            cp_async16(sa + off,  Ag + (size_t)lrow[i] * K_TOT + k0 + lch[i] * 8);
            cp_async16(sbb + off, Bg + (size_t)lrow[i] * K_TOT + k0 + lch[i] * 8);
        }
        cp_async_commit();
    };

    float acc[2][8][4];
    #pragma unroll
    for (int mf = 0; mf < 2; ++mf)
        #pragma unroll
        for (int nf = 0; nf < 8; ++nf)
            #pragma unroll
            for (int j = 0; j < 4; ++j)
                acc[mf][nf][j] = 0.f;

    // prologue
    issue_stage(0, 0);
    issue_stage(1, 1);

    // ldmatrix intra-tile coords (in halves)
    int a_row_base = warp_m * 32 + (lane & 15);                       // + mf*16
    int a_col_base = (lane >> 4) * 8;                                 // + kk*16
    int b_row_base = warp_n * 64 + (lane & 7) + ((lane >> 4) << 3);   // + np*16
    int b_col_base = ((lane >> 3) & 1) * 8;                           // + kk*16

    int s = 0;
    for (int kt = 0; kt < KT; ++kt) {
        cp_async_wait<STAGES - 2>();
        __syncthreads();

        int nx = kt + STAGES - 1;
        if (nx < KT) issue_stage((s + STAGES - 1) % STAGES, nx);

        uint32_t a_base = sb + s * STAGE_BYTES;
        uint32_t b_base = a_base + A_TILE_BYTES;

        #pragma unroll
        for (int kk = 0; kk < 4; ++kk) {
            uint32_t ar[2][4];
            #pragma unroll
            for (int mf = 0; mf < 2; ++mf) {
                uint32_t addr = a_base +
                    (uint32_t)((a_row_base + mf * 16) * SA + kk * 16 + a_col_base) * 2;
                ldsm_x4(ar[mf][0], ar[mf][1], ar[mf][2], ar[mf][3], addr);
            }
            uint32_t br[4][4];   // br[np]: regs {nf=2np:(0,1), nf=2np+1:(2,3)}
            #pragma unroll
            for (int np = 0; np < 4; ++np) {
                uint32_t addr = b_base +
                    (uint32_t)((b_row_base + np * 16) * SA + kk * 16 + b_col_base) * 2;
                ldsm_x4(br[np][0], br[np][1], br[np][2], br[np][3], addr);
            }
            #pragma unroll
            for (int mf = 0; mf < 2; ++mf)
                #pragma unroll
                for (int np = 0; np < 4; ++np) {
                    mma_16816(acc[mf][2*np][0], acc[mf][2*np][1],
                              acc[mf][2*np][2], acc[mf][2*np][3],
                              ar[mf][0], ar[mf][1], ar[mf][2], ar[mf][3],
                              br[np][0], br[np][1]);
                    mma_16816(acc[mf][2*np+1][0], acc[mf][2*np+1][1],
                              acc[mf][2*np+1][2], acc[mf][2*np+1][3],
                              ar[mf][0], ar[mf][1], ar[mf][2], ar[mf][3],
                              br[np][2], br[np][3]);
                }
        }
        if (++s == STAGES) s = 0;
    }

    // epilogue: accum regs -> gmem with bias
    int m0 = pid_m * BM + warp_m * 32 + (lane >> 2);
    int n0 = pid_n * BN + warp_n * 64 + 2 * (lane & 3);
    #pragma unroll
    for (int nf = 0; nf < 8; ++nf) {
        int col = n0 + nf * 8;
        float2 bv = *reinterpret_cast<const float2*>(bias + col);
        #pragma unroll
        for (int mf = 0; mf < 2; ++mf) {
            int row = m0 + mf * 16;
            float2 v0, v1;
            v0.x = acc[mf][nf][0] + bv.x;
            v0.y = acc[mf][nf][1] + bv.y;
            v1.x = acc[mf][nf][2] + bv.x;
            v1.y = acc[mf][nf][3] + bv.y;
            *reinterpret_cast<float2*>(out + (size_t)row * N_TOT + col) = v0;
            *reinterpret_cast<float2*>(out + (size_t)(row + 8) * N_TOT + col) = v1;
        }
    }
}

// ============================ host launch ============================
extern "C" void kernel_launch(void* const* d_in, const int* in_sizes, int n_in,
                              void* d_out, int out_size) {
    const float* x    = (const float*)d_in[0];
    const int*   w    = (const int*)d_in[1];
    const float* sz   = (const float*)d_in[2];
    const float* bias = (const float*)d_in[3];
    float* out = (float*)d_out;

    void* pA = nullptr;
    void* pB = nullptr;
    cudaGetSymbolAddress(&pA, g_A);
    cudaGetSymbolAddress(&pB, g_B);

    cudaFuncSetAttribute(gemm_kernel, cudaFuncAttributeMaxDynamicSharedMemorySize,
                         SMEM_TOTAL_BYTES);

    // 1) fused prep: x f32->f16 and weight dequant->f16
    prep_kernel<<<XB + WB, 256>>>(x, w, sz, (__half*)pA, (__half*)pB);
    // 2) GEMM
    gemm_kernel<<<TILES_M * TILES_N, 256, SMEM_TOTAL_BYTES>>>(bias, out);
}

// round 7
// speedup vs baseline: 1.0137x; 1.0137x over previous
#include <cuda_runtime.h>
#include <cuda_fp16.h>
#include <cstdint>

// ============================ problem constants ============================
#define M_TOT 8192
#define N_TOT 11008
#define K_TOT 4096
#define GSZ   128

#define BM 128
#define BN 128
#define BK 64
#define STAGES 3
#define KT (K_TOT / BK)        // 64
#define TILES_M (M_TOT / BM)   // 64
#define TILES_N (N_TOT / BN)   // 86

#define SA 72                              // padded row pitch in halves (144 B)
#define A_TILE_BYTES (BM * SA * 2)         // 18432
#define B_TILE_BYTES (BN * SA * 2)         // 18432
#define STAGE_BYTES  (A_TILE_BYTES + B_TILE_BYTES)
#define SMEM_TOTAL_BYTES (STAGES * STAGE_BYTES)  // 110592 -> 2 CTAs/SM

// scratch (f16 copies of x and dequantized weight)
__device__ __align__(1024) __half g_A[(size_t)M_TOT * K_TOT];  // 64 MiB
__device__ __align__(1024) __half g_B[(size_t)N_TOT * K_TOT];  // 86 MiB

// ============================ PTX helpers ============================
__device__ __forceinline__ uint32_t smem_to_u32(const void* p) {
    uint32_t a;
    asm("{ .reg .u64 t; cvta.to.shared.u64 t, %1; cvt.u32.u64 %0, t; }"
        : "=r"(a) : "l"(p));
    return a;
}

__device__ __forceinline__ void cp_async16(uint32_t saddr, const void* gptr) {
    asm volatile("cp.async.cg.shared.global [%0], [%1], 16;"
                 :: "r"(saddr), "l"(gptr) : "memory");
}
__device__ __forceinline__ void cp_async_commit() {
    asm volatile("cp.async.commit_group;" ::: "memory");
}
template <int N>
__device__ __forceinline__ void cp_async_wait() {
    asm volatile("cp.async.wait_group %0;" :: "n"(N) : "memory");
}

__device__ __forceinline__ void ldsm_x4(uint32_t& r0, uint32_t& r1,
                                        uint32_t& r2, uint32_t& r3, uint32_t a) {
    asm volatile("ldmatrix.sync.aligned.m8n8.x4.shared.b16 {%0,%1,%2,%3}, [%4];"
                 : "=r"(r0), "=r"(r1), "=r"(r2), "=r"(r3) : "r"(a));
}

__device__ __forceinline__ void mma_16816(float& c0, float& c1, float& c2, float& c3,
                                          uint32_t a0, uint32_t a1, uint32_t a2, uint32_t a3,
                                          uint32_t b0, uint32_t b1) {
    asm volatile(
        "mma.sync.aligned.m16n8k16.row.col.f32.f16.f16.f32 "
        "{%0,%1,%2,%3}, {%4,%5,%6,%7}, {%8,%9}, {%0,%1,%2,%3};"
        : "+f"(c0), "+f"(c1), "+f"(c2), "+f"(c3)
        : "r"(a0), "r"(a1), "r"(a2), "r"(a3), "r"(b0), "r"(b1));
}

// ============================ fused prep kernel ============================
// blocks [0, XB)          : x f32 -> f16
// blocks [XB, XB + WB)    : weight int8(int32) dequant -> f16
#define XB ((int)(((size_t)M_TOT * K_TOT / 8) / 256))   // 16384
#define WB ((int)(((size_t)N_TOT * K_TOT / 8) / 256))   // 22016

__global__ void __launch_bounds__(256) prep_kernel(
    const float* __restrict__ x,
    const int*   __restrict__ w,
    const float* __restrict__ sz,
    __half* __restrict__ oA,
    __half* __restrict__ oB)
{
    int b = blockIdx.x;
    if (b < XB) {
        size_t i = ((size_t)b * 256 + threadIdx.x) * 8;
        float4 a = *reinterpret_cast<const float4*>(x + i);
        float4 c = *reinterpret_cast<const float4*>(x + i + 4);
        __half2 h0 = __floats2half2_rn(a.x, a.y);
        __half2 h1 = __floats2half2_rn(a.z, a.w);
        __half2 h2 = __floats2half2_rn(c.x, c.y);
        __half2 h3 = __floats2half2_rn(c.z, c.w);
        uint4 v;
        v.x = *reinterpret_cast<uint32_t*>(&h0);
        v.y = *reinterpret_cast<uint32_t*>(&h1);
        v.z = *reinterpret_cast<uint32_t*>(&h2);
        v.w = *reinterpret_cast<uint32_t*>(&h3);
        *reinterpret_cast<uint4*>(oA + i) = v;
    } else {
        int idx = (b - XB) * 256 + threadIdx.x;
        int oo = idx >> 9;               // output feature (row)
        int i0 = (idx & 511) << 3;       // start col (8 per thread)
        int g  = i0 >> 7;                // group index
        float2 s2 = reinterpret_cast<const float2*>(sz)[(size_t)g * N_TOT + oo];
        float s = s2.x, z = s2.y;
        size_t base = (size_t)oo * K_TOT + i0;
        int4 wa = reinterpret_cast<const int4*>(w + base)[0];
        int4 wb = reinterpret_cast<const int4*>(w + base)[1];
        __half2 h0 = __floats2half2_rn(wa.x * s + z, wa.y * s + z);
        __half2 h1 = __floats2half2_rn(wa.z * s + z, wa.w * s + z);
        __half2 h2 = __floats2half2_rn(wb.x * s + z, wb.y * s + z);
        __half2 h3 = __floats2half2_rn(wb.z * s + z, wb.w * s + z);
        uint4 v;
        v.x = *reinterpret_cast<uint32_t*>(&h0);
        v.y = *reinterpret_cast<uint32_t*>(&h1);
        v.z = *reinterpret_cast<uint32_t*>(&h2);
        v.w = *reinterpret_cast<uint32_t*>(&h3);
        *reinterpret_cast<uint4*>(oB + base) = v;
    }
}

// ============================ GEMM kernel ============================
// 128 threads = 4 warps; warp grid 2 (m) x 2 (n); warp tile 64x64.
// Fragments double-buffered over kk: LDSM for kk+1 issued BEFORE MMAs for kk,
// so each warp's 32 MMAs hide the next fragment-load latency.
__global__ void __launch_bounds__(128, 2) gemm_kernel(
    const float* __restrict__ bias,
    float* __restrict__ out)
{
    extern __shared__ __align__(128) char smem[];
    uint32_t sb = smem_to_u32(smem);

    int tid = threadIdx.x;
    int wid = tid >> 5;
    int lane = tid & 31;
    int warp_m = wid & 1;    // 0..1
    int warp_n = wid >> 1;   // 0..1

    // L2-friendly raster
    int pid = blockIdx.x;
    const int GROUP_M = 16;
    const int npg = GROUP_M * TILES_N;
    int gidx = pid / npg;
    int r = pid - gidx * npg;
    int pid_m = gidx * GROUP_M + (r % GROUP_M);
    int pid_n = r / GROUP_M;

    const __half* Ag = g_A + (size_t)(pid_m * BM) * K_TOT;
    const __half* Bg = g_B + (size_t)(pid_n * BN) * K_TOT;

    // per-thread load coords: 1024 chunks of 16B per operand per stage; 8 each
    int lrow[8], lch[8];
    #pragma unroll
    for (int i = 0; i < 8; ++i) {
        int idx = tid + i * 128;
        lrow[i] = idx >> 3;
        lch[i]  = idx & 7;
    }

    auto issue_stage = [&](int s, int kt) {
        int k0 = kt * BK;
        uint32_t sa = sb + s * STAGE_BYTES;
        uint32_t sbb = sa + A_TILE_BYTES;
        #pragma unroll
        for (int i = 0; i < 8; ++i) {
            uint32_t off = (uint32_t)(lrow[i] * SA + lch[i] * 8) * 2;
            cp_async16(sa + off,  Ag + (size_t)lrow[i] * K_TOT + k0 + lch[i] * 8);
            cp_async16(sbb + off, Bg + (size_t)lrow[i] * K_TOT + k0 + lch[i] * 8);
        }
        cp_async_commit();
    };

    float acc[4][8][4];
    #pragma unroll
    for (int mf = 0; mf < 4; ++mf)
        #pragma unroll
        for (int nf = 0; nf < 8; ++nf)
            #pragma unroll
            for (int j = 0; j < 4; ++j)
                acc[mf][nf][j] = 0.f;

    // prologue
    issue_stage(0, 0);
    issue_stage(1, 1);

    // ldmatrix intra-tile coords (in halves)
    int a_row_base = warp_m * 64 + (lane & 15);                       // + mf*16
    int a_col_base = (lane >> 4) * 8;                                 // + kk*16
    int b_row_base = warp_n * 64 + (lane & 7) + ((lane >> 4) << 3);   // + np*16
    int b_col_base = ((lane >> 3) & 1) * 8;                           // + kk*16

    // double-buffered fragments
    uint32_t ar[2][4][4];
    uint32_t br[2][4][4];

    auto load_frags = [&](int buf, int kk, uint32_t a_base, uint32_t b_base) {
        #pragma unroll
        for (int mf = 0; mf < 4; ++mf) {
            uint32_t addr = a_base +
                (uint32_t)((a_row_base + mf * 16) * SA + kk * 16 + a_col_base) * 2;
            ldsm_x4(ar[buf][mf][0], ar[buf][mf][1], ar[buf][mf][2], ar[buf][mf][3], addr);
        }
        #pragma unroll
        for (int np = 0; np < 4; ++np) {
            uint32_t addr = b_base +
                (uint32_t)((b_row_base + np * 16) * SA + kk * 16 + b_col_base) * 2;
            ldsm_x4(br[buf][np][0], br[buf][np][1], br[buf][np][2], br[buf][np][3], addr);
        }
    };

    int s = 0;
    for (int kt = 0; kt < KT; ++kt) {
        cp_async_wait<STAGES - 2>();
        __syncthreads();

        uint32_t a_base = sb + s * STAGE_BYTES;
        uint32_t b_base = a_base + A_TILE_BYTES;

        // kk=0 fragments first, then kick off next stage's gmem loads
        load_frags(0, 0, a_base, b_base);

        int nx = kt + STAGES - 1;
        if (nx < KT) issue_stage((s + STAGES - 1) % STAGES, nx);

        #pragma unroll
        for (int kk = 0; kk < 4; ++kk) {
            int cur = kk & 1;
            if (kk < 3) load_frags(cur ^ 1, kk + 1, a_base, b_base);
            #pragma unroll
            for (int mf = 0; mf < 4; ++mf)
                #pragma unroll
                for (int np = 0; np < 4; ++np) {
                    mma_16816(acc[mf][2*np][0], acc[mf][2*np][1],
                              acc[mf][2*np][2], acc[mf][2*np][3],
                              ar[cur][mf][0], ar[cur][mf][1],
                              ar[cur][mf][2], ar[cur][mf][3],
                              br[cur][np][0], br[cur][np][1]);
                    mma_16816(acc[mf][2*np+1][0], acc[mf][2*np+1][1],
                              acc[mf][2*np+1][2], acc[mf][2*np+1][3],
                              ar[cur][mf][0], ar[cur][mf][1],
                              ar[cur][mf][2], ar[cur][mf][3],
                              br[cur][np][2], br[cur][np][3]);
                }
        }
        if (++s == STAGES) s = 0;
    }

    // epilogue: accum regs -> gmem with bias
    int m0 = pid_m * BM + warp_m * 64 + (lane >> 2);
    int n0 = pid_n * BN + warp_n * 64 + 2 * (lane & 3);
    #pragma unroll
    for (int nf = 0; nf < 8; ++nf) {
        int col = n0 + nf * 8;
        float2 bv = *reinterpret_cast<const float2*>(bias + col);
        #pragma unroll
        for (int mf = 0; mf < 4; ++mf) {
            int row = m0 + mf * 16;
            float2 v0, v1;
            v0.x = acc[mf][nf][0] + bv.x;
            v0.y = acc[mf][nf][1] + bv.y;
            v1.x = acc[mf][nf][2] + bv.x;
            v1.y = acc[mf][nf][3] + bv.y;
            *reinterpret_cast<float2*>(out + (size_t)row * N_TOT + col) = v0;
            *reinterpret_cast<float2*>(out + (size_t)(row + 8) * N_TOT + col) = v1;
        }
    }
}

// ============================ host launch ============================
extern "C" void kernel_launch(void* const* d_in, const int* in_sizes, int n_in,
                              void* d_out, int out_size) {
    const float* x    = (const float*)d_in[0];
    const int*   w    = (const int*)d_in[1];
    const float* sz   = (const float*)d_in[2];
    const float* bias = (const float*)d_in[3];
    float* out = (float*)d_out;

    void* pA = nullptr;
    void* pB = nullptr;
    cudaGetSymbolAddress(&pA, g_A);
    cudaGetSymbolAddress(&pB, g_B);

    cudaFuncSetAttribute(gemm_kernel, cudaFuncAttributeMaxDynamicSharedMemorySize,
                         SMEM_TOTAL_BYTES);

    // 1) fused prep: x f32->f16 and weight dequant->f16
    prep_kernel<<<XB + WB, 256>>>(x, w, sz, (__half*)pA, (__half*)pB);
    // 2) GEMM
    gemm_kernel<<<TILES_M * TILES_N, 128, SMEM_TOTAL_BYTES>>>(bias, out);
}